// round 4
// baseline (speedup 1.0000x reference)
#include <cuda_runtime.h>
#include <cstdint>

// Problem constants
#define B_DIM 64
#define T_DIM 32
#define J_DIM 128
#define N_DIM 64
#define IN_F  4096
#define OUT_F 256

// Transposed, tf32-rounded weight: WT[in_f][out_f]
__device__ float g_WT[IN_F * OUT_F];

__device__ __forceinline__ uint32_t f32_to_tf32(float x) {
    uint32_t r;
    asm("cvt.rna.tf32.f32 %0, %1;" : "=r"(r) : "f"(x));
    return r;
}

// ---------------------------------------------------------------------------
// Kernel 1: transpose full_weight (OUT_F, IN_F) -> g_WT (IN_F, OUT_F),
// rounding to tf32 once so the main kernel's gather needs no conversion.
// ---------------------------------------------------------------------------
__global__ void transpose_cvt_kernel(const float* __restrict__ Wfull) {
    __shared__ float tile[32][33];
    int tx = threadIdx.x, ty = threadIdx.y;
    int bx = blockIdx.x;  // IN_F / 32
    int by = blockIdx.y;  // OUT_F / 32
    #pragma unroll
    for (int i = 0; i < 32; i += 8)
        tile[ty + i][tx] = Wfull[(size_t)(by * 32 + ty + i) * IN_F + bx * 32 + tx];
    __syncthreads();
    #pragma unroll
    for (int i = 0; i < 32; i += 8) {
        uint32_t v = f32_to_tf32(tile[tx][ty + i]);
        ((uint32_t*)g_WT)[(size_t)(bx * 32 + ty + i) * OUT_F + by * 32 + tx] = v;
    }
}

// ---------------------------------------------------------------------------
// Kernel 2: per (b,t,mhalf) block: gather W rows, stage X, 64x256x64 GEMM
// via mma.sync.m16n8k8 tf32.
// ---------------------------------------------------------------------------
#define XS_LD 68    // padded stride for Xs [64][68]  -> conflict-free A frags
#define WS_LD 264   // padded stride for Ws [64][264] -> conflict-free B frags

__global__ void __launch_bounds__(256, 2)
masklinear_kernel(const float* __restrict__ X,
                  const int* __restrict__ IDX,   // int32! (jax x64 disabled)
                  float* __restrict__ Y) {
    extern __shared__ float smem[];
    float* Xs = smem;                    // [64][XS_LD]  (M x K, tf32 bits)
    float* Ws = smem + 64 * XS_LD;       // [64][WS_LD]  (K x N, tf32 bits)
    __shared__ int idx_s[64];

    const int blk   = blockIdx.x;
    const int bt    = blk >> 1;          // 0..2047
    const int mhalf = blk & 1;           // which 64-row half of J
    const int b     = bt >> 5;
    const int t     = bt & 31;
    const int tid   = threadIdx.x;
    const int lane  = tid & 31;
    const int wid   = tid >> 5;

    if (tid < 64)
        idx_s[tid] = IDX[((size_t)b * 64 + tid) * 32 + t];

    // Stage X tile: contiguous 64x64 fp32 chunk, convert to tf32 bits.
    const float4* Xg = (const float4*)(X + (size_t)bt * (J_DIM * N_DIM)
                                         + (size_t)mhalf * 64 * N_DIM);
    #pragma unroll
    for (int i = 0; i < 4; i++) {
        int e = tid + i * 256;           // 0..1023 float4s
        float4 v = Xg[e];
        int j  = e >> 4;
        int n4 = (e & 15) * 4;
        uint32_t* dst = (uint32_t*)(Xs + j * XS_LD + n4);
        dst[0] = f32_to_tf32(v.x);
        dst[1] = f32_to_tf32(v.y);
        dst[2] = f32_to_tf32(v.z);
        dst[3] = f32_to_tf32(v.w);
    }
    __syncthreads();  // idx_s visible

    // Gather 64 weight rows (1KB contiguous each, L2-resident).
    #pragma unroll
    for (int r = 0; r < 8; r++) {
        int k = wid + r * 8;
        const float4* src = (const float4*)(g_WT + (size_t)idx_s[k] * OUT_F);
        float4* dst = (float4*)(Ws + k * WS_LD);
        dst[lane]      = src[lane];
        dst[lane + 32] = src[lane + 32];
    }
    __syncthreads();

    // Compute: 8 warps, each 32(M) x 64(N), K = 64 in 8 steps of k8.
    const int wm = wid >> 2;             // 0..1
    const int wn = wid & 3;              // 0..3
    const int m0 = wm * 32;
    const int n0 = wn * 64;
    const int qrow = lane >> 2;          // 0..7
    const int qcol = lane & 3;           // 0..3

    float c[2][8][4];
    #pragma unroll
    for (int mt = 0; mt < 2; mt++)
        #pragma unroll
        for (int nt = 0; nt < 8; nt++)
            #pragma unroll
            for (int i = 0; i < 4; i++) c[mt][nt][i] = 0.f;

    #pragma unroll
    for (int kt = 0; kt < 8; kt++) {
        const int k0 = kt * 8;
        uint32_t a[2][4];
        #pragma unroll
        for (int mt = 0; mt < 2; mt++) {
            const uint32_t* Ab =
                (const uint32_t*)(Xs + (m0 + mt * 16 + qrow) * XS_LD + k0 + qcol);
            a[mt][0] = Ab[0];
            a[mt][1] = Ab[8 * XS_LD];
            a[mt][2] = Ab[4];
            a[mt][3] = Ab[8 * XS_LD + 4];
        }
        uint32_t bf[8][2];
        #pragma unroll
        for (int nt = 0; nt < 8; nt++) {
            const uint32_t* Bb =
                (const uint32_t*)(Ws + (k0 + qcol) * WS_LD + n0 + nt * 8 + qrow);
            bf[nt][0] = Bb[0];
            bf[nt][1] = Bb[4 * WS_LD];
        }
        #pragma unroll
        for (int mt = 0; mt < 2; mt++)
            #pragma unroll
            for (int nt = 0; nt < 8; nt++) {
                asm volatile(
                    "mma.sync.aligned.m16n8k8.row.col.f32.tf32.tf32.f32 "
                    "{%0,%1,%2,%3}, {%4,%5,%6,%7}, {%8,%9}, {%0,%1,%2,%3};\n"
                    : "+f"(c[mt][nt][0]), "+f"(c[mt][nt][1]),
                      "+f"(c[mt][nt][2]), "+f"(c[mt][nt][3])
                    : "r"(a[mt][0]), "r"(a[mt][1]), "r"(a[mt][2]), "r"(a[mt][3]),
                      "r"(bf[nt][0]), "r"(bf[nt][1]));
            }
    }

    // Store: full sectors, float2 per (row, col-pair).
    float* Yb = Y + (size_t)bt * (J_DIM * OUT_F) + (size_t)mhalf * 64 * OUT_F;
    #pragma unroll
    for (int mt = 0; mt < 2; mt++) {
        #pragma unroll
        for (int nt = 0; nt < 8; nt++) {
            int row = m0 + mt * 16 + qrow;
            int col = n0 + nt * 8 + qcol * 2;
            *(float2*)(Yb + (size_t)row * OUT_F + col) =
                make_float2(c[mt][nt][0], c[mt][nt][1]);
            *(float2*)(Yb + (size_t)(row + 8) * OUT_F + col) =
                make_float2(c[mt][nt][2], c[mt][nt][3]);
        }
    }
}

// ---------------------------------------------------------------------------
extern "C" void kernel_launch(void* const* d_in, const int* in_sizes, int n_in,
                              void* d_out, int out_size) {
    const float* X     = (const float*)d_in[0];   // (B,T,J,N) f32
    const int*   IDX   = (const int*)d_in[1];     // (B,N,T) int32 (jax default)
    const float* Wfull = (const float*)d_in[2];   // (OUT_F, IN_F) f32
    float*       Y     = (float*)d_out;           // (B,T,J,OUT_F) f32

    const size_t smem_bytes = (64 * XS_LD + 64 * WS_LD) * sizeof(float); // 84992
    cudaFuncSetAttribute(masklinear_kernel,
                         cudaFuncAttributeMaxDynamicSharedMemorySize,
                         (int)smem_bytes);

    transpose_cvt_kernel<<<dim3(IN_F / 32, OUT_F / 32), dim3(32, 8)>>>(Wfull);
    masklinear_kernel<<<B_DIM * T_DIM * 2, 256, smem_bytes>>>(X, IDX, Y);
}

// round 5
// speedup vs baseline: 1.2391x; 1.2391x over previous
#include <cuda_runtime.h>
#include <cstdint>

// Problem constants
#define B_DIM 64
#define T_DIM 32
#define J_DIM 128
#define N_DIM 64
#define IN_F  4096
#define OUT_F 256

// Transposed, tf32-rounded weight: WT[in_f][out_f]
__device__ float g_WT[IN_F * OUT_F];

__device__ __forceinline__ uint32_t f32_to_tf32(float x) {
    uint32_t r;
    asm("cvt.rna.tf32.f32 %0, %1;" : "=r"(r) : "f"(x));
    return r;
}

__device__ __forceinline__ void cp_async16(void* smem_dst, const void* gsrc) {
    uint32_t d = (uint32_t)__cvta_generic_to_shared(smem_dst);
    asm volatile("cp.async.cg.shared.global [%0], [%1], 16;\n" :: "r"(d), "l"(gsrc));
}
#define CP_COMMIT() asm volatile("cp.async.commit_group;\n" ::: "memory")
#define CP_WAIT0()  asm volatile("cp.async.wait_group 0;\n" ::: "memory")

// ---------------------------------------------------------------------------
// Kernel 1: transpose full_weight (OUT_F, IN_F) -> g_WT (IN_F, OUT_F),
// rounded to tf32 once so the gathered rows need no conversion.
// ---------------------------------------------------------------------------
__global__ void transpose_cvt_kernel(const float* __restrict__ Wfull) {
    __shared__ float tile[32][33];
    int tx = threadIdx.x, ty = threadIdx.y;
    int bx = blockIdx.x;  // IN_F / 32
    int by = blockIdx.y;  // OUT_F / 32
    #pragma unroll
    for (int i = 0; i < 32; i += 8)
        tile[ty + i][tx] = Wfull[(size_t)(by * 32 + ty + i) * IN_F + bx * 32 + tx];
    __syncthreads();
    #pragma unroll
    for (int i = 0; i < 32; i += 8) {
        uint32_t v = f32_to_tf32(tile[tx][ty + i]);
        ((uint32_t*)g_WT)[(size_t)(bx * 32 + ty + i) * OUT_F + by * 32 + tx] = v;
    }
}

// ---------------------------------------------------------------------------
// Kernel 2: persistent CTAs, double-buffered cp.async pipeline.
// Tile per iteration: full (b,t): Y[128 x 256] = X[128 x 64] @ Wg[64 x 256].
// ---------------------------------------------------------------------------
#define XS_LD 68    // padded stride for Xs [128][68] -> conflict-free A frags
#define WS_LD 264   // padded stride for Ws [64][264] -> conflict-free B frags
#define XS_ELEMS (128 * XS_LD)
#define WS_ELEMS (64 * WS_LD)
#define STAGE_ELEMS (XS_ELEMS + WS_ELEMS)
#define NTILES (B_DIM * T_DIM)   // 2048

// Prefetch tile bt into (Xs, Ws): X tile via cp.async, W rows gathered via
// cp.async using warp-local index loads (no extra __syncthreads needed).
__device__ __forceinline__ void prefetch_tile(int bt, float* Xs, float* Ws,
                                              const float* __restrict__ X,
                                              const int* __restrict__ IDX,
                                              int tid, int lane, int wid) {
    const int b = bt >> 5;
    const int t = bt & 31;

    // 1) start idx loads early (lanes 0-3 of each warp own rows 4*wid..4*wid+3)
    int idx_val = 0;
    if (lane < 4)
        idx_val = IDX[((size_t)b * 64 + wid * 4 + lane) * 32 + t];

    // 2) X tile: 128x64 f32 contiguous = 2048 x 16B chunks, 4 per thread
    const float4* Xg = (const float4*)(X + (size_t)bt * (J_DIM * N_DIM));
    #pragma unroll
    for (int i = 0; i < 4; i++) {
        int e = tid + i * 512;
        int j = e >> 4;
        int c = e & 15;
        cp_async16(Xs + j * XS_LD + c * 4, Xg + e);
    }

    // 3) W gather: 4 rows per warp, 8 lanes per row, 8 x 16B chunks per lane
    int rl  = lane >> 3;                               // 0..3 row within warp
    int row = wid * 4 + rl;                            // 0..63
    int idx_r = __shfl_sync(0xffffffffu, idx_val, rl); // broadcast row's index
    const float4* src = (const float4*)(g_WT + (size_t)idx_r * OUT_F);
    float4* dst = (float4*)(Ws + row * WS_LD);
    int c0 = lane & 7;
    #pragma unroll
    for (int i = 0; i < 8; i++)
        cp_async16(dst + c0 + i * 8, src + c0 + i * 8);

    CP_COMMIT();
}

__global__ void __launch_bounds__(512, 1)
masklinear_kernel(const float* __restrict__ X,
                  const int* __restrict__ IDX,
                  float* __restrict__ Y) {
    extern __shared__ float smem[];
    const int tid  = threadIdx.x;
    const int lane = tid & 31;
    const int wid  = tid >> 5;            // 0..15

    // Warp layout: 4(m) x 4(n); warp tile 32 x 64
    const int wm   = wid >> 2;
    const int wn   = wid & 3;
    const int m0   = wm * 32;
    const int n0   = wn * 64;
    const int qrow = lane >> 2;           // 0..7
    const int qcol = lane & 3;            // 0..3

    // Prologue: prefetch first tile into stage 0
    int bt = blockIdx.x;
    prefetch_tile(bt, smem, smem + XS_ELEMS, X, IDX, tid, lane, wid);

    int s = 0;
    for (; bt < NTILES; bt += gridDim.x) {
        CP_WAIT0();
        __syncthreads();

        float* Xs = smem + s * STAGE_ELEMS;
        float* Ws = Xs + XS_ELEMS;

        // Issue prefetch of next tile into the other stage (overlaps compute)
        int nbt = bt + gridDim.x;
        if (nbt < NTILES) {
            float* nXs = smem + (s ^ 1) * STAGE_ELEMS;
            prefetch_tile(nbt, nXs, nXs + XS_ELEMS, X, IDX, tid, lane, wid);
        }

        // ---- Compute: 64 x 256 x 64 per warp-grid, K in 8 steps of k8 ----
        float c[2][8][4];
        #pragma unroll
        for (int mt = 0; mt < 2; mt++)
            #pragma unroll
            for (int nt = 0; nt < 8; nt++)
                #pragma unroll
                for (int i = 0; i < 4; i++) c[mt][nt][i] = 0.f;

        #pragma unroll
        for (int kt = 0; kt < 8; kt++) {
            const int k0 = kt * 8;
            uint32_t a[2][4];
            #pragma unroll
            for (int mt = 0; mt < 2; mt++) {
                const float* Ab = Xs + (m0 + mt * 16 + qrow) * XS_LD + k0 + qcol;
                a[mt][0] = f32_to_tf32(Ab[0]);
                a[mt][1] = f32_to_tf32(Ab[8 * XS_LD]);
                a[mt][2] = f32_to_tf32(Ab[4]);
                a[mt][3] = f32_to_tf32(Ab[8 * XS_LD + 4]);
            }
            uint32_t bf[8][2];
            #pragma unroll
            for (int nt = 0; nt < 8; nt++) {
                const uint32_t* Bb =
                    (const uint32_t*)(Ws + (k0 + qcol) * WS_LD + n0 + nt * 8 + qrow);
                bf[nt][0] = Bb[0];
                bf[nt][1] = Bb[4 * WS_LD];
            }
            #pragma unroll
            for (int mt = 0; mt < 2; mt++)
                #pragma unroll
                for (int nt = 0; nt < 8; nt++) {
                    asm volatile(
                        "mma.sync.aligned.m16n8k8.row.col.f32.tf32.tf32.f32 "
                        "{%0,%1,%2,%3}, {%4,%5,%6,%7}, {%8,%9}, {%0,%1,%2,%3};\n"
                        : "+f"(c[mt][nt][0]), "+f"(c[mt][nt][1]),
                          "+f"(c[mt][nt][2]), "+f"(c[mt][nt][3])
                        : "r"(a[mt][0]), "r"(a[mt][1]), "r"(a[mt][2]), "r"(a[mt][3]),
                          "r"(bf[nt][0]), "r"(bf[nt][1]));
                }
        }

        // ---- Store Y tile (full sectors via float2) ----
        float* Yb = Y + (size_t)bt * (J_DIM * OUT_F);
        #pragma unroll
        for (int mt = 0; mt < 2; mt++) {
            #pragma unroll
            for (int nt = 0; nt < 8; nt++) {
                int row = m0 + mt * 16 + qrow;
                int col = n0 + nt * 8 + qcol * 2;
                *(float2*)(Yb + (size_t)row * OUT_F + col) =
                    make_float2(c[mt][nt][0], c[mt][nt][1]);
                *(float2*)(Yb + (size_t)(row + 8) * OUT_F + col) =
                    make_float2(c[mt][nt][2], c[mt][nt][3]);
            }
        }

        s ^= 1;
    }
}

// ---------------------------------------------------------------------------
extern "C" void kernel_launch(void* const* d_in, const int* in_sizes, int n_in,
                              void* d_out, int out_size) {
    const float* X     = (const float*)d_in[0];   // (B,T,J,N) f32
    const int*   IDX   = (const int*)d_in[1];     // (B,N,T) int32
    const float* Wfull = (const float*)d_in[2];   // (OUT_F, IN_F) f32
    float*       Y     = (float*)d_out;           // (B,T,J,OUT_F) f32

    int nsm = 148;
    cudaDeviceGetAttribute(&nsm, cudaDevAttrMultiProcessorCount, 0);
    if (nsm <= 0 || nsm > NTILES) nsm = 148;

    const size_t smem_bytes = 2 * STAGE_ELEMS * sizeof(float);  // 204800
    cudaFuncSetAttribute(masklinear_kernel,
                         cudaFuncAttributeMaxDynamicSharedMemorySize,
                         (int)smem_bytes);

    transpose_cvt_kernel<<<dim3(IN_F / 32, OUT_F / 32), dim3(32, 8)>>>(Wfull);
    masklinear_kernel<<<nsm, 512, smem_bytes>>>(X, IDX, Y);
}